// round 11
// baseline (speedup 1.0000x reference)
#include <cuda_runtime.h>
#include <cuda_fp16.h>
#include <cstdint>
#include <math.h>

#define NTOK 8192
#define DDIM 1024
#define FDIM 4096
#define NEXP 8

#define BM 128
#define BN 128
#define BK 64        // halves per K-tile
#define THREADS 128  // 4 warps, 2x2 grid of 64x64 warp tiles
#define MAXTILES 71  // worst case sum ceil(cnt_e/128) = 64 + 7

// smem (u32 units): 64 halves = 32 u32 per row + 4 pad = 36 (144B; conflict-free ldsm)
#define ROWU 36
#define A_TILE_U32 (BM * ROWU)           // 4608
#define B_TILE_U32 (BN * ROWU)           // 4608
#define STAGE_U32 (A_TILE_U32 + B_TILE_U32)   // 9216 u32 = 36 KB
#define NSTAGE 3
#define SMEM_BYTES ((NSTAGE * STAGE_U32 + BN) * 4)  // 111104 -> 2 CTAs/SM

// ---------------- device scratch (static, allocation-free) ----------------
__device__ __half g_X16[(size_t)NTOK * DDIM];           // x in fp16
__device__ __half g_H16[(size_t)(NTOK + BM) * FDIM];    // permuted hidden acts (fp16, padded)
__device__ __half g_W1T[(size_t)NEXP * FDIM * DDIM];    // W1 transposed [e][n][k] fp16
__device__ __half g_W2T[(size_t)NEXP * DDIM * FDIM];    // W2 transposed [e][n][k] fp16
__device__ int   g_eid[NTOK];
__device__ float g_gate[NTOK];
__device__ int   g_counts[NEXP];
__device__ int   g_cursor[NEXP];
__device__ int   g_offsets[NEXP + 1];
__device__ int   g_tile_e[MAXTILES];
__device__ int   g_tile_row[MAXTILES];
__device__ int   g_ntiles;
__device__ int   g_perm[NTOK];

// ---------------- helpers ----------------
__device__ __forceinline__ uint32_t h2u(__half2 h) {
    uint32_t u;
    memcpy(&u, &h, 4);
    return u;
}

__device__ __forceinline__ void mma16(float* c, const uint32_t* a, uint32_t b0, uint32_t b1) {
    asm volatile(
        "mma.sync.aligned.m16n8k16.row.col.f32.f16.f16.f32 "
        "{%0,%1,%2,%3}, {%4,%5,%6,%7}, {%8,%9}, {%0,%1,%2,%3};\n"
        : "+f"(c[0]), "+f"(c[1]), "+f"(c[2]), "+f"(c[3])
        : "r"(a[0]), "r"(a[1]), "r"(a[2]), "r"(a[3]), "r"(b0), "r"(b1));
}

__device__ __forceinline__ void ldsm4(uint32_t* r, uint32_t addr) {
    asm volatile("ldmatrix.sync.aligned.m8n8.x4.shared.b16 {%0,%1,%2,%3}, [%4];"
                 : "=r"(r[0]), "=r"(r[1]), "=r"(r[2]), "=r"(r[3]) : "r"(addr));
}

__device__ __forceinline__ void cp16(void* dst, const void* src, bool pred) {
    uint32_t d = (uint32_t)__cvta_generic_to_shared(dst);
    int sz = pred ? 16 : 0;   // src-size 0 -> zero-fill 16B
    asm volatile("cp.async.cg.shared.global [%0], [%1], 16, %2;\n" :: "r"(d), "l"(src), "r"(sz));
}
__device__ __forceinline__ void cp_commit() { asm volatile("cp.async.commit_group;\n"); }
template<int N> __device__ __forceinline__ void cp_wait() {
    asm volatile("cp.async.wait_group %0;\n" :: "n"(N));
}

// ---------------- pre-pass kernels ----------------
// Weight convert + transpose: W [e][KD][ND] fp32 -> WT [e][ND][KD] fp16.
// ZERO: block (0,0,0) also zeroes the routing counters.
template<int KD, int ND, bool ZERO>
__global__ void __launch_bounds__(256)
wcvt_kernel(const float* __restrict__ W, __half* __restrict__ WT) {
    __shared__ __half s[64][66];
    int t = threadIdx.x;
    if (ZERO && blockIdx.x == 0 && blockIdx.y == 0 && blockIdx.z == 0 && t < NEXP) {
        g_counts[t] = 0;
        g_cursor[t] = 0;
    }
    int e = blockIdx.z;
    int n0 = blockIdx.x * 64, k0 = blockIdx.y * 64;
    const float* Wb = W + (size_t)e * KD * ND;
    __half* WTb = WT + (size_t)e * ND * KD;
    int f4 = t & 15, g16 = t >> 4;
#pragma unroll
    for (int it = 0; it < 4; it++) {
        int kl = it * 16 + g16;
        float4 v = *(const float4*)(Wb + (size_t)(k0 + kl) * ND + n0 + f4 * 4);
        __half2* d = (__half2*)&s[kl][f4 * 4];
        d[0] = __floats2half2_rn(v.x, v.y);
        d[1] = __floats2half2_rn(v.z, v.w);
    }
    __syncthreads();
#pragma unroll
    for (int it = 0; it < 4; it++) {
        int nl = it * 16 + g16;
        __half h[4];
#pragma unroll
        for (int j = 0; j < 4; j++) h[j] = s[f4 * 4 + j][nl];
        *(uint2*)(WTb + (size_t)(n0 + nl) * KD + k0 + f4 * 4) = *(uint2*)h;
    }
}

// Router fused with x->fp16 conversion (x is read once anyway).
__global__ void router_kernel(const float* __restrict__ x,
                              const float* __restrict__ Wr,
                              const float* __restrict__ br) {
    __shared__ float sWrT[NEXP * DDIM];  // transposed: [e][d]
    int tid = threadIdx.x;
    for (int i = tid; i < NEXP * DDIM; i += 256) {
        int d = i >> 3, e = i & 7;
        sWrT[e * DDIM + d] = Wr[i];
    }
    __syncthreads();

    int warp = tid >> 5, lane = tid & 31;
    int tok = blockIdx.x * 8 + warp;
    const float4* xr = (const float4*)(x + (size_t)tok * DDIM);
    uint2* xo = (uint2*)(g_X16 + (size_t)tok * DDIM);

    float acc[NEXP];
#pragma unroll
    for (int e = 0; e < NEXP; e++) acc[e] = 0.f;
#pragma unroll
    for (int it = 0; it < 8; it++) {
        int d4 = lane + it * 32;
        float4 xv = xr[d4];
        uint2 w;
        w.x = h2u(__floats2half2_rn(xv.x, xv.y));
        w.y = h2u(__floats2half2_rn(xv.z, xv.w));
        xo[d4] = w;
#pragma unroll
        for (int e = 0; e < NEXP; e++) {
            float4 wv = ((const float4*)(sWrT + e * DDIM))[d4];
            acc[e] += xv.x * wv.x + xv.y * wv.y + xv.z * wv.z + xv.w * wv.w;
        }
    }
#pragma unroll
    for (int e = 0; e < NEXP; e++)
#pragma unroll
        for (int o = 16; o; o >>= 1) acc[e] += __shfl_xor_sync(0xffffffffu, acc[e], o);

    if (lane == 0) {
        float l[NEXP];
#pragma unroll
        for (int e = 0; e < NEXP; e++) l[e] = acc[e] + br[e];
        int best = 0;
#pragma unroll
        for (int e = 1; e < NEXP; e++) if (l[e] > l[best]) best = e;  // first-max like jnp.argmax
        float mx = l[best];
        float se = 0.f;
#pragma unroll
        for (int e = 0; e < NEXP; e++) se += expf(l[e] - mx);
        g_eid[tok] = best;
        g_gate[tok] = 1.0f / se;  // exp(0)/se
        atomicAdd(&g_counts[best], 1);
    }
}

// Scatter fused with plan.
__global__ void scatter_kernel() {
    __shared__ int soff[NEXP];
    if (threadIdx.x == 0) {
        int off = 0;
#pragma unroll
        for (int e = 0; e < NEXP; e++) { soff[e] = off; off += g_counts[e]; }
    }
    __syncthreads();

    if (blockIdx.x == 0 && threadIdx.x == 0) {
        int off = 0, nt = 0;
        g_offsets[0] = 0;
        for (int e = 0; e < NEXP; e++) {
            int c = g_counts[e];
            int start = off;
            off += c;
            g_offsets[e + 1] = off;
            int tiles = (c + BM - 1) >> 7;
            for (int i = 0; i < tiles; i++) { g_tile_e[nt] = e; g_tile_row[nt] = start + i * BM; nt++; }
        }
        g_ntiles = nt;
    }

    int t = blockIdx.x * 256 + threadIdx.x;
    if (t < NTOK) {
        int e = g_eid[t];
        int p = atomicAdd(&g_cursor[e], 1);
        g_perm[soff[e] + p] = t;
    }
}

// ---------------- grouped fp16 GEMM ----------------
// 128 threads/CTA, 2x2 warp grid of 64x64 warp tiles (halves fragment smem traffic
// vs 64x32: bytes/MAC 0.094 -> 0.0625, lifting the smem-crossbar cap on tensor%).
// G1: A = gather(g_X16, perm) [K=DDIM], B = g_W1T[e] (n-major), epi gelu -> g_H16
// G2: A = g_H16 (contiguous) [K=FDIM], B = g_W2T[e], epi gate*scatter -> out (fp32)
template<int KTOT, int NTOT, int NT, bool G1>
__global__ void __launch_bounds__(THREADS, 2)
moe_gemm_kernel(const __half* __restrict__ WT, const float* __restrict__ bias,
                float* __restrict__ Outglob) {
    int mt = blockIdx.x / NT;
    int ntile = blockIdx.x % NT;
    if (mt >= g_ntiles) return;
    int e = g_tile_e[mt];
    int row0 = g_tile_row[mt];
    int rows = g_offsets[e + 1] - row0;
    if (rows > BM) rows = BM;
    int n0 = ntile * BN;

    const __half* Abase = G1 ? g_X16 : g_H16;
    const __half* Bw = WT + (size_t)e * KTOT * NTOT;

    extern __shared__ uint32_t sm32[];
    float* sbias = (float*)(sm32 + NSTAGE * STAGE_U32);
    uint32_t shb = (uint32_t)__cvta_generic_to_shared(sm32);

    int tid = threadIdx.x;
    int srow = tid >> 3, j = tid & 7;      // staging: 16 rows/pass, 16B chunk j

    // A loader: 8 rows/thread (srow + i*16), chunk j (8 halves at k = j*8)
    const __half* aptr[8];
    bool avalid[8];
#pragma unroll
    for (int i = 0; i < 8; i++) {
        int r = srow + i * 16;
        bool v = r < rows;
        int src;
        if (G1) { src = g_perm[row0 + (v ? r : 0)]; avalid[i] = v; }
        else    { src = row0 + r; avalid[i] = true; }   // g_H16 padded
        aptr[i] = Abase + (size_t)src * KTOT + j * 8;
    }
    // B loader: 8 rows/thread (srow + i*16); WT rows are k-contiguous
    const __half* bptr = Bw + (size_t)(n0 + srow) * KTOT + j * 8;

    sbias[tid] = bias[(size_t)e * NTOT + n0 + tid];   // BN == 128 == blockDim

    float c[4][8][4];
#pragma unroll
    for (int mf = 0; mf < 4; mf++)
#pragma unroll
        for (int nf = 0; nf < 8; nf++)
#pragma unroll
            for (int i = 0; i < 4; i++) c[mf][nf][i] = 0.f;

    int wid = tid >> 5, lane = tid & 31;
    int wm = wid & 1, wn = wid >> 1;        // 2 x 2 warp grid, 64x64 warp tile
    int mbase = wm * 64, nbase = wn * 64;
    int g = lane >> 2, t4 = lane & 3;

    // ldmatrix lane address bases (byte addresses into shared space)
    int l7 = lane & 7;
    // A: mats (m0-7,k0-7),(m8-15,k0-7),(m0-7,k8-15),(m8-15,k8-15)
    uint32_t aAddr = shb + (((mbase + l7 + ((lane >> 3) & 1) * 8) * ROWU) + ((lane >> 4) & 1) * 4) * 4;
    // B: mats (n0-7,k0-7),(n0-7,k8-15),(n8-15,k0-7),(n8-15,k8-15)
    uint32_t bAddr = shb + A_TILE_U32 * 4 +
                     (((nbase + l7 + ((lane >> 4) & 1) * 8) * ROWU) + ((lane >> 3) & 1) * 4) * 4;

    constexpr int KT = KTOT / BK;
    constexpr uint32_t STB = STAGE_U32 * 4;   // stage stride in bytes

    // ---- staging helper ----
    auto stage = [&](uint32_t* dst, int k0) {
#pragma unroll
        for (int i = 0; i < 8; i++)
            cp16(dst + (srow + i * 16) * ROWU + j * 4, aptr[i] + k0, avalid[i]);
#pragma unroll
        for (int i = 0; i < 8; i++)
            cp16(dst + A_TILE_U32 + (srow + i * 16) * ROWU + j * 4,
                 bptr + (size_t)i * 16 * KTOT + k0, true);
    };

    // prologue: stage tiles 0 and 1 (KT >= 16 always)
    stage(sm32, 0);
    cp_commit();
    stage(sm32 + STAGE_U32, BK);
    cp_commit();

    int cur = 0, nxt = 2;   // compute buffer t%3; prefetch buffer (t+2)%3
    for (int t = 0; t < KT; t++) {
        cp_wait<1>();            // group for tile t (issued 2 iters ago) complete
        __syncthreads();         // publish tile t; all warps done reading buf nxt
        if (t + 2 < KT)
            stage(sm32 + nxt * STAGE_U32, (t + 2) * BK);
        cp_commit();             // one group per iteration, even if empty

        uint32_t sb = cur * STB;
#pragma unroll
        for (int ks = 0; ks < 4; ks++) {       // 4 x k16 per 64-K tile
            uint32_t ko = ks * 32;             // 16 halves = 32 bytes
            uint32_t afr[4][4], bfr[4][4];
#pragma unroll
            for (int mf = 0; mf < 4; mf++)
                ldsm4(afr[mf], aAddr + sb + mf * (16 * ROWU * 4) + ko);
#pragma unroll
            for (int np = 0; np < 4; np++)
                ldsm4(bfr[np], bAddr + sb + np * (16 * ROWU * 4) + ko);
#pragma unroll
            for (int np = 0; np < 4; np++) {
#pragma unroll
                for (int mf = 0; mf < 4; mf++) {
                    mma16(c[mf][2 * np],     afr[mf], bfr[np][0], bfr[np][1]);
                    mma16(c[mf][2 * np + 1], afr[mf], bfr[np][2], bfr[np][3]);
                }
            }
        }
        cur = (cur == 2) ? 0 : cur + 1;
        nxt = (nxt == 2) ? 0 : nxt + 1;
    }

    // ---- epilogue ----
#pragma unroll
    for (int mf = 0; mf < 4; mf++) {
#pragma unroll
        for (int half = 0; half < 2; half++) {
            int ml = mbase + mf * 16 + g + half * 8;
            if (ml >= rows) continue;
            size_t grow;
            float gate = 1.f;
            if (G1) {
                grow = (size_t)(row0 + ml);
            } else {
                int tok = g_perm[row0 + ml];
                gate = g_gate[tok];
                grow = (size_t)tok;
            }
#pragma unroll
            for (int nf = 0; nf < 8; nf++) {
                int nl = nbase + nf * 8 + t4 * 2;
                float vx = c[mf][nf][half * 2 + 0] + sbias[nl];
                float vy = c[mf][nf][half * 2 + 1] + sbias[nl + 1];
                if (G1) {
                    vx = 0.5f * vx * (1.0f + erff(vx * 0.70710678118654752f));
                    vy = 0.5f * vy * (1.0f + erff(vy * 0.70710678118654752f));
                    __half2* orow = (__half2*)(g_H16 + grow * NTOT + n0 + nl);
                    *orow = __floats2half2_rn(vx, vy);
                } else {
                    float2 v = { vx * gate, vy * gate };
                    *(float2*)(Outglob + grow * NTOT + n0 + nl) = v;
                }
            }
        }
    }
}

// ---------------- launch ----------------
// Order (ncu profiles launch index 3): wcvt1, router, scatter, GEMM1, wcvt2, GEMM2
extern "C" void kernel_launch(void* const* d_in, const int* in_sizes, int n_in,
                              void* d_out, int out_size) {
    const float* x  = (const float*)d_in[0];
    const float* W1 = (const float*)d_in[1];
    const float* b1 = (const float*)d_in[2];
    const float* W2 = (const float*)d_in[3];
    const float* b2 = (const float*)d_in[4];
    const float* Wr = (const float*)d_in[5];
    const float* br = (const float*)d_in[6];
    float* out = (float*)d_out;

    __half *w1t, *w2t;
    cudaGetSymbolAddress((void**)&w1t, g_W1T);
    cudaGetSymbolAddress((void**)&w2t, g_W2T);

    cudaFuncSetAttribute(moe_gemm_kernel<DDIM, FDIM, FDIM/BN, true>,
                         cudaFuncAttributeMaxDynamicSharedMemorySize, SMEM_BYTES);
    cudaFuncSetAttribute(moe_gemm_kernel<FDIM, DDIM, DDIM/BN, false>,
                         cudaFuncAttributeMaxDynamicSharedMemorySize, SMEM_BYTES);

    wcvt_kernel<DDIM, FDIM, true><<<dim3(FDIM/64, DDIM/64, NEXP), 256>>>(W1, w1t);
    router_kernel<<<NTOK / 8, 256>>>(x, Wr, br);
    scatter_kernel<<<NTOK / 256, 256>>>();

    moe_gemm_kernel<DDIM, FDIM, FDIM/BN, true>
        <<<(FDIM/BN) * MAXTILES, THREADS, SMEM_BYTES>>>(w1t, b1, nullptr);

    wcvt_kernel<FDIM, DDIM, false><<<dim3(DDIM/64, FDIM/64, NEXP), 256>>>(W2, w2t);

    moe_gemm_kernel<FDIM, DDIM, DDIM/BN, false>
        <<<(DDIM/BN) * MAXTILES, THREADS, SMEM_BYTES>>>(w2t, b2, out);
}

// round 12
// speedup vs baseline: 1.0349x; 1.0349x over previous
#include <cuda_runtime.h>
#include <cuda_fp16.h>
#include <cstdint>
#include <math.h>

#define NTOK 8192
#define DDIM 1024
#define FDIM 4096
#define NEXP 8

#define BM 128
#define BN 128
#define BK 64        // halves per K-tile
#define MAXTILES 71  // worst case sum ceil(cnt_e/128) = 64 + 7

// smem (u32 units): 64 halves = 32 u32 per row + 4 pad = 36 (144B; conflict-free ldsm)
#define ROWU 36
#define A_TILE_U32 (BM * ROWU)           // 4608
#define B_TILE_U32 (BN * ROWU)           // 4608
#define STAGE_U32 (A_TILE_U32 + B_TILE_U32)   // 9216 u32 = 36 KB
#define NSTAGE 3
#define SMEM_BYTES ((NSTAGE * STAGE_U32 + BN) * 4)  // 111104 -> 2 CTAs/SM

#define WC1_BLOCKS ((FDIM/64) * (DDIM/64) * NEXP)   // 8192 (W1 convert)
#define WC2_BLOCKS ((DDIM/64) * (FDIM/64) * NEXP)   // 8192 (W2 convert)
#define NG1 ((FDIM/BN) * MAXTILES)                  // 2272 GEMM1 blocks

// ---------------- device scratch (static, allocation-free) ----------------
__device__ __half g_X16[(size_t)NTOK * DDIM];           // x in fp16
__device__ __half g_H16[(size_t)(NTOK + BM) * FDIM];    // permuted hidden acts (fp16, padded)
__device__ __half g_W1T[(size_t)NEXP * FDIM * DDIM];    // W1 transposed [e][n][k] fp16
__device__ __half g_W2T[(size_t)NEXP * DDIM * FDIM];    // W2 transposed [e][n][k] fp16
__device__ int   g_eid[NTOK];
__device__ float g_gate[NTOK];
__device__ int   g_counts[NEXP];
__device__ int   g_cursor[NEXP];
__device__ int   g_offsets[NEXP + 1];
__device__ int   g_tile_e[MAXTILES];
__device__ int   g_tile_row[MAXTILES];
__device__ int   g_ntiles;
__device__ int   g_perm[NTOK];

// ---------------- helpers ----------------
__device__ __forceinline__ uint32_t h2u(__half2 h) {
    uint32_t u;
    memcpy(&u, &h, 4);
    return u;
}

__device__ __forceinline__ void mma16(float* c, const uint32_t* a, uint32_t b0, uint32_t b1) {
    asm volatile(
        "mma.sync.aligned.m16n8k16.row.col.f32.f16.f16.f32 "
        "{%0,%1,%2,%3}, {%4,%5,%6,%7}, {%8,%9}, {%0,%1,%2,%3};\n"
        : "+f"(c[0]), "+f"(c[1]), "+f"(c[2]), "+f"(c[3])
        : "r"(a[0]), "r"(a[1]), "r"(a[2]), "r"(a[3]), "r"(b0), "r"(b1));
}

__device__ __forceinline__ void ldsm4(uint32_t* r, uint32_t addr) {
    asm volatile("ldmatrix.sync.aligned.m8n8.x4.shared.b16 {%0,%1,%2,%3}, [%4];"
                 : "=r"(r[0]), "=r"(r[1]), "=r"(r[2]), "=r"(r[3]) : "r"(addr));
}

__device__ __forceinline__ void cp16(void* dst, const void* src, bool pred) {
    uint32_t d = (uint32_t)__cvta_generic_to_shared(dst);
    int sz = pred ? 16 : 0;   // src-size 0 -> zero-fill 16B
    asm volatile("cp.async.cg.shared.global [%0], [%1], 16, %2;\n" :: "r"(d), "l"(src), "r"(sz));
}
__device__ __forceinline__ void cp_commit() { asm volatile("cp.async.commit_group;\n"); }
template<int N> __device__ __forceinline__ void cp_wait() {
    asm volatile("cp.async.wait_group %0;\n" :: "n"(N));
}

// ---------------- weight convert body (shared by both fused launches) ----------------
// W [e][KD][ND] fp32 -> WT [e][ND][KD] fp16; one 64x64 tile per block (256 threads).
template<int KD, int ND>
__device__ __forceinline__ void wcvt_body(const float* __restrict__ W, __half* __restrict__ WT,
                                          int bid, void* smem_raw) {
    __half (*s)[66] = (__half (*)[66])smem_raw;   // 64 x 66 halves = 8448 B
    constexpr int NBLK = ND / 64;
    constexpr int KBLK = KD / 64;
    int nb = bid % NBLK;
    int kb = (bid / NBLK) % KBLK;
    int e  = bid / (NBLK * KBLK);
    int n0 = nb * 64, k0 = kb * 64;
    const float* Wb = W + (size_t)e * KD * ND;
    __half* WTb = WT + (size_t)e * ND * KD;
    int t = threadIdx.x;
    int f4 = t & 15, g16 = t >> 4;
#pragma unroll
    for (int it = 0; it < 4; it++) {
        int kl = it * 16 + g16;
        float4 v = *(const float4*)(Wb + (size_t)(k0 + kl) * ND + n0 + f4 * 4);
        __half2* d = (__half2*)&s[kl][f4 * 4];
        d[0] = __floats2half2_rn(v.x, v.y);
        d[1] = __floats2half2_rn(v.z, v.w);
    }
    __syncthreads();
#pragma unroll
    for (int it = 0; it < 4; it++) {
        int nl = it * 16 + g16;
        __half h[4];
#pragma unroll
        for (int j = 0; j < 4; j++) h[j] = s[f4 * 4 + j][nl];
        *(uint2*)(WTb + (size_t)(n0 + nl) * KD + k0 + f4 * 4) = *(uint2*)h;
    }
}

// ---------------- fused pre-pass: wcvt1 blocks + router blocks in one launch ----------
__global__ void __launch_bounds__(256)
pre_kernel(const float* __restrict__ x, const float* __restrict__ Wr,
           const float* __restrict__ br, const float* __restrict__ W1,
           __half* __restrict__ w1t) {
    __shared__ __align__(16) float sWrT[NEXP * DDIM];   // 32 KB (wcvt uses first 8.4 KB)

    if (blockIdx.x < WC1_BLOCKS) {
        wcvt_body<DDIM, FDIM>(W1, w1t, blockIdx.x, sWrT);
        return;
    }
    int bid = blockIdx.x - WC1_BLOCKS;

    // ---- router (fused with x->fp16 conversion) ----
    int tid = threadIdx.x;
    for (int i = tid; i < NEXP * DDIM; i += 256) {
        int d = i >> 3, e = i & 7;
        sWrT[e * DDIM + d] = Wr[i];
    }
    __syncthreads();

    int warp = tid >> 5, lane = tid & 31;
    int tok = bid * 8 + warp;
    const float4* xr = (const float4*)(x + (size_t)tok * DDIM);
    uint2* xo = (uint2*)(g_X16 + (size_t)tok * DDIM);

    float acc[NEXP];
#pragma unroll
    for (int e = 0; e < NEXP; e++) acc[e] = 0.f;
#pragma unroll
    for (int it = 0; it < 8; it++) {
        int d4 = lane + it * 32;
        float4 xv = xr[d4];
        uint2 w;
        w.x = h2u(__floats2half2_rn(xv.x, xv.y));
        w.y = h2u(__floats2half2_rn(xv.z, xv.w));
        xo[d4] = w;
#pragma unroll
        for (int e = 0; e < NEXP; e++) {
            float4 wv = ((const float4*)(sWrT + e * DDIM))[d4];
            acc[e] += xv.x * wv.x + xv.y * wv.y + xv.z * wv.z + xv.w * wv.w;
        }
    }
#pragma unroll
    for (int e = 0; e < NEXP; e++)
#pragma unroll
        for (int o = 16; o; o >>= 1) acc[e] += __shfl_xor_sync(0xffffffffu, acc[e], o);

    if (lane == 0) {
        float l[NEXP];
#pragma unroll
        for (int e = 0; e < NEXP; e++) l[e] = acc[e] + br[e];
        int best = 0;
#pragma unroll
        for (int e = 1; e < NEXP; e++) if (l[e] > l[best]) best = e;  // first-max like jnp.argmax
        float mx = l[best];
        float se = 0.f;
#pragma unroll
        for (int e = 0; e < NEXP; e++) se += expf(l[e] - mx);
        g_eid[tok] = best;
        g_gate[tok] = 1.0f / se;  // exp(0)/se
        atomicAdd(&g_counts[best], 1);
    }
}

// ---------------- scatter fused with plan ----------------
__global__ void scatter_kernel() {
    __shared__ int soff[NEXP];
    if (threadIdx.x == 0) {
        int off = 0;
#pragma unroll
        for (int e = 0; e < NEXP; e++) { soff[e] = off; off += g_counts[e]; }
    }
    __syncthreads();

    if (blockIdx.x == 0 && threadIdx.x == 0) {
        int off = 0, nt = 0;
        g_offsets[0] = 0;
        for (int e = 0; e < NEXP; e++) {
            int c = g_counts[e];
            int start = off;
            off += c;
            g_offsets[e + 1] = off;
            int tiles = (c + BM - 1) >> 7;
            for (int i = 0; i < tiles; i++) { g_tile_e[nt] = e; g_tile_row[nt] = start + i * BM; nt++; }
        }
        g_ntiles = nt;
    }

    int t = blockIdx.x * 256 + threadIdx.x;
    if (t < NTOK) {
        int e = g_eid[t];
        int p = atomicAdd(&g_cursor[e], 1);
        g_perm[soff[e] + p] = t;
    }
}

// ---------------- grouped fp16 GEMM (m16n8k16 + ldmatrix, 128x128x64, 3-stage, 2 CTA/SM) ----
// Round-10 winning geometry: 256 thr, 2x4 warps of 64x32.
// G1 (FUSEW=true): blocks >= NG1 instead run the W2 convert (overlaps GEMM1's tail).
// G1: A = gather(g_X16, perm) [K=DDIM], B = g_W1T[e], epi gelu -> g_H16
// G2: A = g_H16 (contiguous) [K=FDIM], B = g_W2T[e], epi gate*scatter -> out (fp32)
template<int KTOT, int NTOT, int NT, bool G1, bool FUSEW>
__global__ void __launch_bounds__(256, 2)
moe_gemm_kernel(const __half* __restrict__ WT, const float* __restrict__ bias,
                float* __restrict__ Outglob,
                const float* __restrict__ Wsrc, __half* __restrict__ Wdst) {
    extern __shared__ uint32_t sm32[];

    if (FUSEW) {
        if (blockIdx.x >= NG1) {
            wcvt_body<FDIM, DDIM>(Wsrc, Wdst, blockIdx.x - NG1, (void*)sm32);
            return;
        }
    }

    int mt = blockIdx.x / NT;
    int ntile = blockIdx.x % NT;
    if (mt >= g_ntiles) return;
    int e = g_tile_e[mt];
    int row0 = g_tile_row[mt];
    int rows = g_offsets[e + 1] - row0;
    if (rows > BM) rows = BM;
    int n0 = ntile * BN;

    const __half* Abase = G1 ? g_X16 : g_H16;
    const __half* Bw = WT + (size_t)e * KTOT * NTOT;

    float* sbias = (float*)(sm32 + NSTAGE * STAGE_U32);
    uint32_t shb = (uint32_t)__cvta_generic_to_shared(sm32);

    int tid = threadIdx.x;
    int srow = tid >> 3, j = tid & 7;      // staging: 32 rows/pass, 16B chunk j

    // A loader: 4 rows/thread (srow + i*32), chunk j (8 halves at k = j*8)
    const __half* aptr[4];
    bool avalid[4];
#pragma unroll
    for (int i = 0; i < 4; i++) {
        int r = srow + i * 32;
        bool v = r < rows;
        int src;
        if (G1) { src = g_perm[row0 + (v ? r : 0)]; avalid[i] = v; }
        else    { src = row0 + r; avalid[i] = true; }   // g_H16 padded
        aptr[i] = Abase + (size_t)src * KTOT + j * 8;
    }
    // B loader: 4 rows/thread (srow + i*32); WT rows are k-contiguous
    const __half* bptr = Bw + (size_t)(n0 + srow) * KTOT + j * 8;

    if (tid < BN) sbias[tid] = bias[(size_t)e * NTOT + n0 + tid];

    float c[4][4][4];
#pragma unroll
    for (int mf = 0; mf < 4; mf++)
#pragma unroll
        for (int nf = 0; nf < 4; nf++)
#pragma unroll
            for (int i = 0; i < 4; i++) c[mf][nf][i] = 0.f;

    int wid = tid >> 5, lane = tid & 31;
    int wm = wid & 1, wn = wid >> 1;        // 2 x 4 warp grid, 64x32 warp tile
    int mbase = wm * 64, nbase = wn * 32;
    int g = lane >> 2, t4 = lane & 3;

    // ldmatrix lane address bases (byte addresses into shared space)
    int l7 = lane & 7;
    // A: mats (m0-7,k0-7),(m8-15,k0-7),(m0-7,k8-15),(m8-15,k8-15)
    uint32_t aAddr = shb + (((mbase + l7 + ((lane >> 3) & 1) * 8) * ROWU) + ((lane >> 4) & 1) * 4) * 4;
    // B: mats (n0-7,k0-7),(n0-7,k8-15),(n8-15,k0-7),(n8-15,k8-15)
    uint32_t bAddr = shb + A_TILE_U32 * 4 +
                     (((nbase + l7 + ((lane >> 4) & 1) * 8) * ROWU) + ((lane >> 3) & 1) * 4) * 4;

    constexpr int KT = KTOT / BK;
    constexpr uint32_t STB = STAGE_U32 * 4;   // stage stride in bytes

    // ---- staging helper ----
    auto stage = [&](uint32_t* dst, int k0) {
#pragma unroll
        for (int i = 0; i < 4; i++)
            cp16(dst + (srow + i * 32) * ROWU + j * 4, aptr[i] + k0, avalid[i]);
#pragma unroll
        for (int i = 0; i < 4; i++)
            cp16(dst + A_TILE_U32 + (srow + i * 32) * ROWU + j * 4,
                 bptr + (size_t)i * 32 * KTOT + k0, true);
    };

    // prologue: stage tiles 0 and 1 (KT >= 16 always)
    stage(sm32, 0);
    cp_commit();
    stage(sm32 + STAGE_U32, BK);
    cp_commit();

    int cur = 0, nxt = 2;   // compute buffer t%3; prefetch buffer (t+2)%3
    for (int t = 0; t < KT; t++) {
        cp_wait<1>();            // group for tile t (issued 2 iters ago) complete
        __syncthreads();         // publish tile t; all warps done reading buf nxt
        if (t + 2 < KT)
            stage(sm32 + nxt * STAGE_U32, (t + 2) * BK);
        cp_commit();             // one group per iteration, even if empty

        uint32_t sb = cur * STB;
#pragma unroll
        for (int ks = 0; ks < 4; ks++) {       // 4 x k16 per 64-K tile
            uint32_t ko = ks * 32;             // 16 halves = 32 bytes
            uint32_t afr[4][4], bfr[2][4];
#pragma unroll
            for (int mf = 0; mf < 4; mf++)
                ldsm4(afr[mf], aAddr + sb + mf * (16 * ROWU * 4) + ko);
#pragma unroll
            for (int np = 0; np < 2; np++)
                ldsm4(bfr[np], bAddr + sb + np * (16 * ROWU * 4) + ko);
#pragma unroll
            for (int np = 0; np < 2; np++) {
#pragma unroll
                for (int mf = 0; mf < 4; mf++) {
                    mma16(c[mf][2 * np],     afr[mf], bfr[np][0], bfr[np][1]);
                    mma16(c[mf][2 * np + 1], afr[mf], bfr[np][2], bfr[np][3]);
                }
            }
        }
        cur = (cur == 2) ? 0 : cur + 1;
        nxt = (nxt == 2) ? 0 : nxt + 1;
    }

    // ---- epilogue ----
#pragma unroll
    for (int mf = 0; mf < 4; mf++) {
#pragma unroll
        for (int half = 0; half < 2; half++) {
            int ml = mbase + mf * 16 + g + half * 8;
            if (ml >= rows) continue;
            size_t grow;
            float gate = 1.f;
            if (G1) {
                grow = (size_t)(row0 + ml);
            } else {
                int tok = g_perm[row0 + ml];
                gate = g_gate[tok];
                grow = (size_t)tok;
            }
#pragma unroll
            for (int nf = 0; nf < 4; nf++) {
                int nl = nbase + nf * 8 + t4 * 2;
                float vx = c[mf][nf][half * 2 + 0] + sbias[nl];
                float vy = c[mf][nf][half * 2 + 1] + sbias[nl + 1];
                if (G1) {
                    vx = 0.5f * vx * (1.0f + erff(vx * 0.70710678118654752f));
                    vy = 0.5f * vy * (1.0f + erff(vy * 0.70710678118654752f));
                    __half2* orow = (__half2*)(g_H16 + grow * NTOT + n0 + nl);
                    *orow = __floats2half2_rn(vx, vy);
                } else {
                    float2 v = { vx * gate, vy * gate };
                    *(float2*)(Outglob + grow * NTOT + n0 + nl) = v;
                }
            }
        }
    }
}

// ---------------- launch ----------------
// 4 kernels: pre(0: wcvt1+router), scatter(1), GEMM1+wcvt2(2), GEMM2(3 <- ncu profiles this)
extern "C" void kernel_launch(void* const* d_in, const int* in_sizes, int n_in,
                              void* d_out, int out_size) {
    const float* x  = (const float*)d_in[0];
    const float* W1 = (const float*)d_in[1];
    const float* b1 = (const float*)d_in[2];
    const float* W2 = (const float*)d_in[3];
    const float* b2 = (const float*)d_in[4];
    const float* Wr = (const float*)d_in[5];
    const float* br = (const float*)d_in[6];
    float* out = (float*)d_out;

    __half *w1t, *w2t;
    int *cnts, *curs;
    cudaGetSymbolAddress((void**)&w1t, g_W1T);
    cudaGetSymbolAddress((void**)&w2t, g_W2T);
    cudaGetSymbolAddress((void**)&cnts, g_counts);
    cudaGetSymbolAddress((void**)&curs, g_cursor);

    cudaFuncSetAttribute(moe_gemm_kernel<DDIM, FDIM, FDIM/BN, true, true>,
                         cudaFuncAttributeMaxDynamicSharedMemorySize, SMEM_BYTES);
    cudaFuncSetAttribute(moe_gemm_kernel<FDIM, DDIM, DDIM/BN, false, false>,
                         cudaFuncAttributeMaxDynamicSharedMemorySize, SMEM_BYTES);

    cudaMemsetAsync(cnts, 0, NEXP * sizeof(int));
    cudaMemsetAsync(curs, 0, NEXP * sizeof(int));

    pre_kernel<<<WC1_BLOCKS + NTOK / 8, 256>>>(x, Wr, br, W1, w1t);
    scatter_kernel<<<NTOK / 256, 256>>>();

    moe_gemm_kernel<DDIM, FDIM, FDIM/BN, true, true>
        <<<NG1 + WC2_BLOCKS, 256, SMEM_BYTES>>>(w1t, b1, nullptr, W2, w2t);

    moe_gemm_kernel<FDIM, DDIM, DDIM/BN, false, false>
        <<<(DDIM/BN) * MAXTILES, 256, SMEM_BYTES>>>(w2t, b2, out, nullptr, nullptr);
}

// round 13
// speedup vs baseline: 1.1773x; 1.1376x over previous
#include <cuda_runtime.h>
#include <cuda_fp16.h>
#include <cstdint>
#include <math.h>

#define NTOK 8192
#define DDIM 1024
#define FDIM 4096
#define NEXP 8

#define BM 128
#define BN 128
#define BK 64        // halves per K-tile
#define MAXTILES 71  // worst case sum ceil(cnt_e/128) = 64 + 7

// smem (u32 units): 64 halves = 32 u32 per row + 4 pad = 36 (144B; conflict-free ldsm)
#define ROWU 36
#define A_TILE_U32 (BM * ROWU)           // 4608
#define B_TILE_U32 (BN * ROWU)           // 4608
#define STAGE_U32 (A_TILE_U32 + B_TILE_U32)   // 9216 u32 = 36 KB
#define NSTAGE 3
#define SMEM_BYTES ((NSTAGE * STAGE_U32 + BN) * 4)  // 111104 -> 2 CTAs/SM

#define WC1_BLOCKS ((FDIM/64) * (DDIM/64) * NEXP)   // 8192 (W1 convert)
#define WC2_BLOCKS ((DDIM/64) * (FDIM/64) * NEXP)   // 8192 (W2 convert)
#define NG1 ((FDIM/BN) * MAXTILES)                  // 2272 GEMM1 blocks

// ---------------- device scratch (static, allocation-free) ----------------
__device__ __half g_X16[(size_t)NTOK * DDIM];           // x in fp16
__device__ __half g_H16[(size_t)(NTOK + BM) * FDIM];    // permuted hidden acts (fp16, padded)
__device__ __half g_W1T[(size_t)NEXP * FDIM * DDIM];    // W1 transposed [e][n][k] fp16
__device__ __half g_W2T[(size_t)NEXP * DDIM * FDIM];    // W2 transposed [e][n][k] fp16
__device__ int   g_eid[NTOK];
__device__ float g_gate[NTOK];
__device__ int   g_counts[NEXP];
__device__ int   g_cursor[NEXP];
__device__ int   g_offsets[NEXP + 1];
__device__ int   g_tile_e[MAXTILES];
__device__ int   g_tile_row[MAXTILES];
__device__ int   g_ntiles;
__device__ int   g_perm[NTOK];

// ---------------- helpers ----------------
__device__ __forceinline__ uint32_t h2u(__half2 h) {
    uint32_t u;
    memcpy(&u, &h, 4);
    return u;
}

__device__ __forceinline__ void mma16(float* c, const uint32_t* a, uint32_t b0, uint32_t b1) {
    asm volatile(
        "mma.sync.aligned.m16n8k16.row.col.f32.f16.f16.f32 "
        "{%0,%1,%2,%3}, {%4,%5,%6,%7}, {%8,%9}, {%0,%1,%2,%3};\n"
        : "+f"(c[0]), "+f"(c[1]), "+f"(c[2]), "+f"(c[3])
        : "r"(a[0]), "r"(a[1]), "r"(a[2]), "r"(a[3]), "r"(b0), "r"(b1));
}

__device__ __forceinline__ void ldsm4(uint32_t* r, uint32_t addr) {
    asm volatile("ldmatrix.sync.aligned.m8n8.x4.shared.b16 {%0,%1,%2,%3}, [%4];"
                 : "=r"(r[0]), "=r"(r[1]), "=r"(r[2]), "=r"(r[3]) : "r"(addr));
}

__device__ __forceinline__ void cp16(void* dst, const void* src, bool pred) {
    uint32_t d = (uint32_t)__cvta_generic_to_shared(dst);
    int sz = pred ? 16 : 0;   // src-size 0 -> zero-fill 16B
    asm volatile("cp.async.cg.shared.global [%0], [%1], 16, %2;\n" :: "r"(d), "l"(src), "r"(sz));
}
__device__ __forceinline__ void cp_commit() { asm volatile("cp.async.commit_group;\n"); }
template<int N> __device__ __forceinline__ void cp_wait() {
    asm volatile("cp.async.wait_group %0;\n" :: "n"(N));
}

// ---------------- weight convert body (shared by both fused launches) ----------------
// W [e][KD][ND] fp32 -> WT [e][ND][KD] fp16; one 64x64 tile per block (256 threads).
template<int KD, int ND>
__device__ __forceinline__ void wcvt_body(const float* __restrict__ W, __half* __restrict__ WT,
                                          int bid, void* smem_raw) {
    __half (*s)[66] = (__half (*)[66])smem_raw;   // 64 x 66 halves = 8448 B
    constexpr int NBLK = ND / 64;
    constexpr int KBLK = KD / 64;
    int nb = bid % NBLK;
    int kb = (bid / NBLK) % KBLK;
    int e  = bid / (NBLK * KBLK);
    int n0 = nb * 64, k0 = kb * 64;
    const float* Wb = W + (size_t)e * KD * ND;
    __half* WTb = WT + (size_t)e * ND * KD;
    int t = threadIdx.x;
    int f4 = t & 15, g16 = t >> 4;
#pragma unroll
    for (int it = 0; it < 4; it++) {
        int kl = it * 16 + g16;
        float4 v = *(const float4*)(Wb + (size_t)(k0 + kl) * ND + n0 + f4 * 4);
        __half2* d = (__half2*)&s[kl][f4 * 4];
        d[0] = __floats2half2_rn(v.x, v.y);
        d[1] = __floats2half2_rn(v.z, v.w);
    }
    __syncthreads();
#pragma unroll
    for (int it = 0; it < 4; it++) {
        int nl = it * 16 + g16;
        __half h[4];
#pragma unroll
        for (int j = 0; j < 4; j++) h[j] = s[f4 * 4 + j][nl];
        *(uint2*)(WTb + (size_t)(n0 + nl) * KD + k0 + f4 * 4) = *(uint2*)h;
    }
}

// ---------------- fused pre-pass: wcvt1 blocks + router blocks in one launch ----------
__global__ void __launch_bounds__(256)
pre_kernel(const float* __restrict__ x, const float* __restrict__ Wr,
           const float* __restrict__ br, const float* __restrict__ W1,
           __half* __restrict__ w1t) {
    __shared__ __align__(16) float sWrT[NEXP * DDIM];   // 32 KB (wcvt uses first 8.4 KB)

    if (blockIdx.x < WC1_BLOCKS) {
        wcvt_body<DDIM, FDIM>(W1, w1t, blockIdx.x, sWrT);
        return;
    }
    int bid = blockIdx.x - WC1_BLOCKS;

    // ---- router (fused with x->fp16 conversion) ----
    int tid = threadIdx.x;
    for (int i = tid; i < NEXP * DDIM; i += 256) {
        int d = i >> 3, e = i & 7;
        sWrT[e * DDIM + d] = Wr[i];
    }
    __syncthreads();

    int warp = tid >> 5, lane = tid & 31;
    int tok = bid * 8 + warp;
    const float4* xr = (const float4*)(x + (size_t)tok * DDIM);
    uint2* xo = (uint2*)(g_X16 + (size_t)tok * DDIM);

    float acc[NEXP];
#pragma unroll
    for (int e = 0; e < NEXP; e++) acc[e] = 0.f;
#pragma unroll
    for (int it = 0; it < 8; it++) {
        int d4 = lane + it * 32;
        float4 xv = xr[d4];
        uint2 w;
        w.x = h2u(__floats2half2_rn(xv.x, xv.y));
        w.y = h2u(__floats2half2_rn(xv.z, xv.w));
        xo[d4] = w;
#pragma unroll
        for (int e = 0; e < NEXP; e++) {
            float4 wv = ((const float4*)(sWrT + e * DDIM))[d4];
            acc[e] += xv.x * wv.x + xv.y * wv.y + xv.z * wv.z + xv.w * wv.w;
        }
    }
#pragma unroll
    for (int e = 0; e < NEXP; e++)
#pragma unroll
        for (int o = 16; o; o >>= 1) acc[e] += __shfl_xor_sync(0xffffffffu, acc[e], o);

    if (lane == 0) {
        float l[NEXP];
#pragma unroll
        for (int e = 0; e < NEXP; e++) l[e] = acc[e] + br[e];
        int best = 0;
#pragma unroll
        for (int e = 1; e < NEXP; e++) if (l[e] > l[best]) best = e;  // first-max like jnp.argmax
        float mx = l[best];
        float se = 0.f;
#pragma unroll
        for (int e = 0; e < NEXP; e++) se += expf(l[e] - mx);
        g_eid[tok] = best;
        g_gate[tok] = 1.0f / se;  // exp(0)/se
        atomicAdd(&g_counts[best], 1);
    }
}

// ---------------- scatter fused with plan ----------------
__global__ void scatter_kernel() {
    __shared__ int soff[NEXP];
    if (threadIdx.x == 0) {
        int off = 0;
#pragma unroll
        for (int e = 0; e < NEXP; e++) { soff[e] = off; off += g_counts[e]; }
    }
    __syncthreads();

    if (blockIdx.x == 0 && threadIdx.x == 0) {
        int off = 0, nt = 0;
        g_offsets[0] = 0;
        for (int e = 0; e < NEXP; e++) {
            int c = g_counts[e];
            int start = off;
            off += c;
            g_offsets[e + 1] = off;
            int tiles = (c + BM - 1) >> 7;
            for (int i = 0; i < tiles; i++) { g_tile_e[nt] = e; g_tile_row[nt] = start + i * BM; nt++; }
        }
        g_ntiles = nt;
    }

    int t = blockIdx.x * 256 + threadIdx.x;
    if (t < NTOK) {
        int e = g_eid[t];
        int p = atomicAdd(&g_cursor[e], 1);
        g_perm[soff[e] + p] = t;
    }
}

// ---------------- grouped fp16 GEMM (m16n8k16 + ldmatrix, 128x128x64, 3-stage, 2 CTA/SM) ----
// Staging for tile t+2 is issued in 4 chunks interleaved with the 4 k16 compute steps,
// so cp.async writes drain through the smem crossbar DURING MMA execution instead of
// as an exclusive post-barrier burst (which starved the tensor pipe -> 55% wall).
// G1 (FUSEW=true): blocks >= NG1 instead run the W2 convert (overlaps GEMM1's tail).
// G1: A = gather(g_X16, perm) [K=DDIM], B = g_W1T[e], epi gelu -> g_H16
// G2: A = g_H16 (contiguous) [K=FDIM], B = g_W2T[e], epi gate*scatter -> out (fp32)
template<int KTOT, int NTOT, int NT, bool G1, bool FUSEW>
__global__ void __launch_bounds__(256, 2)
moe_gemm_kernel(const __half* __restrict__ WT, const float* __restrict__ bias,
                float* __restrict__ Outglob,
                const float* __restrict__ Wsrc, __half* __restrict__ Wdst) {
    extern __shared__ uint32_t sm32[];

    if (FUSEW) {
        if (blockIdx.x >= NG1) {
            wcvt_body<FDIM, DDIM>(Wsrc, Wdst, blockIdx.x - NG1, (void*)sm32);
            return;
        }
    }

    int mt = blockIdx.x / NT;
    int ntile = blockIdx.x % NT;
    if (mt >= g_ntiles) return;
    int e = g_tile_e[mt];
    int row0 = g_tile_row[mt];
    int rows = g_offsets[e + 1] - row0;
    if (rows > BM) rows = BM;
    int n0 = ntile * BN;

    const __half* Abase = G1 ? g_X16 : g_H16;
    const __half* Bw = WT + (size_t)e * KTOT * NTOT;

    float* sbias = (float*)(sm32 + NSTAGE * STAGE_U32);
    uint32_t shb = (uint32_t)__cvta_generic_to_shared(sm32);

    int tid = threadIdx.x;
    int srow = tid >> 3, j = tid & 7;      // staging: 32 rows/chunk, 16B chunk j

    // A loader: 4 rows/thread (srow + i*32), chunk j (8 halves at k = j*8)
    const __half* aptr[4];
    bool avalid[4];
#pragma unroll
    for (int i = 0; i < 4; i++) {
        int r = srow + i * 32;
        bool v = r < rows;
        int src;
        if (G1) { src = g_perm[row0 + (v ? r : 0)]; avalid[i] = v; }
        else    { src = row0 + r; avalid[i] = true; }   // g_H16 padded
        aptr[i] = Abase + (size_t)src * KTOT + j * 8;
    }
    // B loader: 4 rows/thread (srow + i*32); WT rows are k-contiguous
    const __half* bptr = Bw + (size_t)(n0 + srow) * KTOT + j * 8;

    if (tid < BN) sbias[tid] = bias[(size_t)e * NTOT + n0 + tid];

    float c[4][4][4];
#pragma unroll
    for (int mf = 0; mf < 4; mf++)
#pragma unroll
        for (int nf = 0; nf < 4; nf++)
#pragma unroll
            for (int i = 0; i < 4; i++) c[mf][nf][i] = 0.f;

    int wid = tid >> 5, lane = tid & 31;
    int wm = wid & 1, wn = wid >> 1;        // 2 x 4 warp grid, 64x32 warp tile
    int mbase = wm * 64, nbase = wn * 32;
    int g = lane >> 2, t4 = lane & 3;

    // ldmatrix lane address bases (byte addresses into shared space)
    int l7 = lane & 7;
    // A: mats (m0-7,k0-7),(m8-15,k0-7),(m0-7,k8-15),(m8-15,k8-15)
    uint32_t aAddr = shb + (((mbase + l7 + ((lane >> 3) & 1) * 8) * ROWU) + ((lane >> 4) & 1) * 4) * 4;
    // B: mats (n0-7,k0-7),(n0-7,k8-15),(n8-15,k0-7),(n8-15,k8-15)
    uint32_t bAddr = shb + A_TILE_U32 * 4 +
                     (((nbase + l7 + ((lane >> 4) & 1) * 8) * ROWU) + ((lane >> 3) & 1) * 4) * 4;

    constexpr int KT = KTOT / BK;
    constexpr uint32_t STB = STAGE_U32 * 4;   // stage stride in bytes

    // ---- staging: one chunk = 1 A row-set + 1 B row-set (1/4 of a tile) ----
    auto stage_chunk = [&](uint32_t* dst, int k0, int i) {
        cp16(dst + (srow + i * 32) * ROWU + j * 4, aptr[i] + k0, avalid[i]);
        cp16(dst + A_TILE_U32 + (srow + i * 32) * ROWU + j * 4,
             bptr + (size_t)i * 32 * KTOT + k0, true);
    };
    auto stage_full = [&](uint32_t* dst, int k0) {
#pragma unroll
        for (int i = 0; i < 4; i++) stage_chunk(dst, k0, i);
    };

    // prologue: stage tiles 0 and 1 (KT >= 16 always)
    stage_full(sm32, 0);
    cp_commit();
    stage_full(sm32 + STAGE_U32, BK);
    cp_commit();

    int cur = 0, nxt = 2;   // compute buffer t%3; prefetch buffer (t+2)%3
    for (int t = 0; t < KT; t++) {
        cp_wait<1>();            // group for tile t (issued 2 iters ago) complete
        __syncthreads();         // publish tile t; all warps done reading buf nxt

        bool pf = (t + 2 < KT);
        uint32_t* dst = sm32 + nxt * STAGE_U32;
        int pk0 = (t + 2) * BK;
        uint32_t sb = cur * STB;

#pragma unroll
        for (int ks = 0; ks < 4; ks++) {       // 4 x k16 per 64-K tile
            uint32_t ko = ks * 32;             // 16 halves = 32 bytes
            uint32_t afr[4][4], bfr[2][4];
#pragma unroll
            for (int mf = 0; mf < 4; mf++)
                ldsm4(afr[mf], aAddr + sb + mf * (16 * ROWU * 4) + ko);
#pragma unroll
            for (int np = 0; np < 2; np++)
                ldsm4(bfr[np], bAddr + sb + np * (16 * ROWU * 4) + ko);

            if (pf) stage_chunk(dst, pk0, ks);  // writes drain while MMAs execute

#pragma unroll
            for (int np = 0; np < 2; np++) {
#pragma unroll
                for (int mf = 0; mf < 4; mf++) {
                    mma16(c[mf][2 * np],     afr[mf], bfr[np][0], bfr[np][1]);
                    mma16(c[mf][2 * np + 1], afr[mf], bfr[np][2], bfr[np][3]);
                }
            }
        }
        cp_commit();             // one group per iteration, even if empty
        cur = (cur == 2) ? 0 : cur + 1;
        nxt = (nxt == 2) ? 0 : nxt + 1;
    }

    // ---- epilogue ----
#pragma unroll
    for (int mf = 0; mf < 4; mf++) {
#pragma unroll
        for (int half = 0; half < 2; half++) {
            int ml = mbase + mf * 16 + g + half * 8;
            if (ml >= rows) continue;
            size_t grow;
            float gate = 1.f;
            if (G1) {
                grow = (size_t)(row0 + ml);
            } else {
                int tok = g_perm[row0 + ml];
                gate = g_gate[tok];
                grow = (size_t)tok;
            }
#pragma unroll
            for (int nf = 0; nf < 4; nf++) {
                int nl = nbase + nf * 8 + t4 * 2;
                float vx = c[mf][nf][half * 2 + 0] + sbias[nl];
                float vy = c[mf][nf][half * 2 + 1] + sbias[nl + 1];
                if (G1) {
                    vx = 0.5f * vx * (1.0f + erff(vx * 0.70710678118654752f));
                    vy = 0.5f * vy * (1.0f + erff(vy * 0.70710678118654752f));
                    __half2* orow = (__half2*)(g_H16 + grow * NTOT + n0 + nl);
                    *orow = __floats2half2_rn(vx, vy);
                } else {
                    float2 v = { vx * gate, vy * gate };
                    *(float2*)(Outglob + grow * NTOT + n0 + nl) = v;
                }
            }
        }
    }
}

// ---------------- launch ----------------
// 4 kernels: pre(0: wcvt1+router), scatter(1), GEMM1+wcvt2(2), GEMM2(3 <- ncu profiles this)
extern "C" void kernel_launch(void* const* d_in, const int* in_sizes, int n_in,
                              void* d_out, int out_size) {
    const float* x  = (const float*)d_in[0];
    const float* W1 = (const float*)d_in[1];
    const float* b1 = (const float*)d_in[2];
    const float* W2 = (const float*)d_in[3];
    const float* b2 = (const float*)d_in[4];
    const float* Wr = (const float*)d_in[5];
    const float* br = (const float*)d_in[6];
    float* out = (float*)d_out;

    __half *w1t, *w2t;
    int *cnts, *curs;
    cudaGetSymbolAddress((void**)&w1t, g_W1T);
    cudaGetSymbolAddress((void**)&w2t, g_W2T);
    cudaGetSymbolAddress((void**)&cnts, g_counts);
    cudaGetSymbolAddress((void**)&curs, g_cursor);

    cudaFuncSetAttribute(moe_gemm_kernel<DDIM, FDIM, FDIM/BN, true, true>,
                         cudaFuncAttributeMaxDynamicSharedMemorySize, SMEM_BYTES);
    cudaFuncSetAttribute(moe_gemm_kernel<FDIM, DDIM, DDIM/BN, false, false>,
                         cudaFuncAttributeMaxDynamicSharedMemorySize, SMEM_BYTES);

    cudaMemsetAsync(cnts, 0, NEXP * sizeof(int));
    cudaMemsetAsync(curs, 0, NEXP * sizeof(int));

    pre_kernel<<<WC1_BLOCKS + NTOK / 8, 256>>>(x, Wr, br, W1, w1t);
    scatter_kernel<<<NTOK / 256, 256>>>();

    moe_gemm_kernel<DDIM, FDIM, FDIM/BN, true, true>
        <<<NG1 + WC2_BLOCKS, 256, SMEM_BYTES>>>(w1t, b1, nullptr, W2, w2t);

    moe_gemm_kernel<FDIM, DDIM, DDIM/BN, false, false>
        <<<(DDIM/BN) * MAXTILES, 256, SMEM_BYTES>>>(w2t, b2, out, nullptr, nullptr);
}

// round 14
// speedup vs baseline: 1.2107x; 1.0284x over previous
#include <cuda_runtime.h>
#include <cuda_fp16.h>
#include <cstdint>
#include <math.h>

#define NTOK 8192
#define DDIM 1024
#define FDIM 4096
#define NEXP 8

#define BM 128
#define BN 128
#define BK 64        // halves per K-tile
#define MAXTILES 71  // worst case sum ceil(cnt_e/128) = 64 + 7

// smem (u32 units): 64 halves = 32 u32 per row + 4 pad = 36 (144B; conflict-free ldsm)
#define ROWU 36
#define A_TILE_U32 (BM * ROWU)           // 4608
#define B_TILE_U32 (BN * ROWU)           // 4608
#define STAGE_U32 (A_TILE_U32 + B_TILE_U32)   // 9216 u32 = 36 KB
#define NSTAGE 3
#define MB_U32 (NSTAGE * STAGE_U32 + BN)            // u32 offset of mbarriers
#define SMEM_BYTES ((MB_U32 + 16) * 4)              // +48B mbarriers -> 111152, 2 CTAs/SM

#define WC1_BLOCKS ((FDIM/64) * (DDIM/64) * NEXP)   // 8192 (W1 convert)
#define WC2_BLOCKS ((DDIM/64) * (FDIM/64) * NEXP)   // 8192 (W2 convert)
#define NG1 ((FDIM/BN) * MAXTILES)                  // 2272 GEMM1 blocks

// ---------------- device scratch (static, allocation-free) ----------------
__device__ __half g_X16[(size_t)NTOK * DDIM];           // x in fp16
__device__ __half g_H16[(size_t)(NTOK + BM) * FDIM];    // permuted hidden acts (fp16, padded)
__device__ __half g_W1T[(size_t)NEXP * FDIM * DDIM];    // W1 transposed [e][n][k] fp16
__device__ __half g_W2T[(size_t)NEXP * DDIM * FDIM];    // W2 transposed [e][n][k] fp16
__device__ int   g_eid[NTOK];
__device__ float g_gate[NTOK];
__device__ int   g_counts[NEXP];
__device__ int   g_cursor[NEXP];
__device__ int   g_offsets[NEXP + 1];
__device__ int   g_tile_e[MAXTILES];
__device__ int   g_tile_row[MAXTILES];
__device__ int   g_ntiles;
__device__ int   g_perm[NTOK];

// ---------------- helpers ----------------
__device__ __forceinline__ uint32_t h2u(__half2 h) {
    uint32_t u;
    memcpy(&u, &h, 4);
    return u;
}

__device__ __forceinline__ void mma16(float* c, const uint32_t* a, uint32_t b0, uint32_t b1) {
    asm volatile(
        "mma.sync.aligned.m16n8k16.row.col.f32.f16.f16.f32 "
        "{%0,%1,%2,%3}, {%4,%5,%6,%7}, {%8,%9}, {%0,%1,%2,%3};\n"
        : "+f"(c[0]), "+f"(c[1]), "+f"(c[2]), "+f"(c[3])
        : "r"(a[0]), "r"(a[1]), "r"(a[2]), "r"(a[3]), "r"(b0), "r"(b1));
}

__device__ __forceinline__ void ldsm4(uint32_t* r, uint32_t addr) {
    asm volatile("ldmatrix.sync.aligned.m8n8.x4.shared.b16 {%0,%1,%2,%3}, [%4];"
                 : "=r"(r[0]), "=r"(r[1]), "=r"(r[2]), "=r"(r[3]) : "r"(addr));
}

__device__ __forceinline__ void cp16(void* dst, const void* src, bool pred) {
    uint32_t d = (uint32_t)__cvta_generic_to_shared(dst);
    int sz = pred ? 16 : 0;   // src-size 0 -> zero-fill 16B
    asm volatile("cp.async.cg.shared.global [%0], [%1], 16, %2;\n" :: "r"(d), "l"(src), "r"(sz));
}

// ---- mbarrier pipeline primitives (sm_80/90 PTX, fine on base sm_103) ----
__device__ __forceinline__ void mbar_init(uint32_t a, uint32_t cnt) {
    asm volatile("mbarrier.init.shared.b64 [%0], %1;" :: "r"(a), "r"(cnt) : "memory");
}
__device__ __forceinline__ void mbar_arrive(uint32_t a) {
    asm volatile("mbarrier.arrive.release.cta.shared::cta.b64 _, [%0];" :: "r"(a) : "memory");
}
// arrive on mbarrier when ALL prior cp.async of this thread have completed
__device__ __forceinline__ void cp_arrive(uint32_t a) {
    asm volatile("cp.async.mbarrier.arrive.noinc.shared::cta.b64 [%0];" :: "r"(a) : "memory");
}
__device__ __forceinline__ void mbar_wait(uint32_t a, uint32_t parity) {
    asm volatile(
        "{ .reg .pred P;\n"
        "W_%=:\n"
        "mbarrier.try_wait.parity.acquire.cta.shared::cta.b64 P, [%0], %1, 0x989680;\n"
        "@P bra D_%=;\n"
        "bra W_%=;\n"
        "D_%=:\n}"
        :: "r"(a), "r"(parity) : "memory");
}

// ---------------- weight convert body (shared by both fused launches) ----------------
// W [e][KD][ND] fp32 -> WT [e][ND][KD] fp16; one 64x64 tile per block (256 threads).
template<int KD, int ND>
__device__ __forceinline__ void wcvt_body(const float* __restrict__ W, __half* __restrict__ WT,
                                          int bid, void* smem_raw) {
    __half (*s)[66] = (__half (*)[66])smem_raw;   // 64 x 66 halves = 8448 B
    constexpr int NBLK = ND / 64;
    constexpr int KBLK = KD / 64;
    int nb = bid % NBLK;
    int kb = (bid / NBLK) % KBLK;
    int e  = bid / (NBLK * KBLK);
    int n0 = nb * 64, k0 = kb * 64;
    const float* Wb = W + (size_t)e * KD * ND;
    __half* WTb = WT + (size_t)e * ND * KD;
    int t = threadIdx.x;
    int f4 = t & 15, g16 = t >> 4;
#pragma unroll
    for (int it = 0; it < 4; it++) {
        int kl = it * 16 + g16;
        float4 v = *(const float4*)(Wb + (size_t)(k0 + kl) * ND + n0 + f4 * 4);
        __half2* d = (__half2*)&s[kl][f4 * 4];
        d[0] = __floats2half2_rn(v.x, v.y);
        d[1] = __floats2half2_rn(v.z, v.w);
    }
    __syncthreads();
#pragma unroll
    for (int it = 0; it < 4; it++) {
        int nl = it * 16 + g16;
        __half h[4];
#pragma unroll
        for (int j = 0; j < 4; j++) h[j] = s[f4 * 4 + j][nl];
        *(uint2*)(WTb + (size_t)(n0 + nl) * KD + k0 + f4 * 4) = *(uint2*)h;
    }
}

// ---------------- fused pre-pass: wcvt1 blocks + router blocks in one launch ----------
__global__ void __launch_bounds__(256)
pre_kernel(const float* __restrict__ x, const float* __restrict__ Wr,
           const float* __restrict__ br, const float* __restrict__ W1,
           __half* __restrict__ w1t) {
    __shared__ __align__(16) float sWrT[NEXP * DDIM];   // 32 KB (wcvt uses first 8.4 KB)

    if (blockIdx.x < WC1_BLOCKS) {
        wcvt_body<DDIM, FDIM>(W1, w1t, blockIdx.x, sWrT);
        return;
    }
    int bid = blockIdx.x - WC1_BLOCKS;

    // ---- router (fused with x->fp16 conversion) ----
    int tid = threadIdx.x;
    for (int i = tid; i < NEXP * DDIM; i += 256) {
        int d = i >> 3, e = i & 7;
        sWrT[e * DDIM + d] = Wr[i];
    }
    __syncthreads();

    int warp = tid >> 5, lane = tid & 31;
    int tok = bid * 8 + warp;
    const float4* xr = (const float4*)(x + (size_t)tok * DDIM);
    uint2* xo = (uint2*)(g_X16 + (size_t)tok * DDIM);

    float acc[NEXP];
#pragma unroll
    for (int e = 0; e < NEXP; e++) acc[e] = 0.f;
#pragma unroll
    for (int it = 0; it < 8; it++) {
        int d4 = lane + it * 32;
        float4 xv = xr[d4];
        uint2 w;
        w.x = h2u(__floats2half2_rn(xv.x, xv.y));
        w.y = h2u(__floats2half2_rn(xv.z, xv.w));
        xo[d4] = w;
#pragma unroll
        for (int e = 0; e < NEXP; e++) {
            float4 wv = ((const float4*)(sWrT + e * DDIM))[d4];
            acc[e] += xv.x * wv.x + xv.y * wv.y + xv.z * wv.z + xv.w * wv.w;
        }
    }
#pragma unroll
    for (int e = 0; e < NEXP; e++)
#pragma unroll
        for (int o = 16; o; o >>= 1) acc[e] += __shfl_xor_sync(0xffffffffu, acc[e], o);

    if (lane == 0) {
        float l[NEXP];
#pragma unroll
        for (int e = 0; e < NEXP; e++) l[e] = acc[e] + br[e];
        int best = 0;
#pragma unroll
        for (int e = 1; e < NEXP; e++) if (l[e] > l[best]) best = e;  // first-max like jnp.argmax
        float mx = l[best];
        float se = 0.f;
#pragma unroll
        for (int e = 0; e < NEXP; e++) se += expf(l[e] - mx);
        g_eid[tok] = best;
        g_gate[tok] = 1.0f / se;  // exp(0)/se
        atomicAdd(&g_counts[best], 1);
    }
}

// ---------------- scatter fused with plan ----------------
__global__ void scatter_kernel() {
    __shared__ int soff[NEXP];
    if (threadIdx.x == 0) {
        int off = 0;
#pragma unroll
        for (int e = 0; e < NEXP; e++) { soff[e] = off; off += g_counts[e]; }
    }
    __syncthreads();

    if (blockIdx.x == 0 && threadIdx.x == 0) {
        int off = 0, nt = 0;
        g_offsets[0] = 0;
        for (int e = 0; e < NEXP; e++) {
            int c = g_counts[e];
            int start = off;
            off += c;
            g_offsets[e + 1] = off;
            int tiles = (c + BM - 1) >> 7;
            for (int i = 0; i < tiles; i++) { g_tile_e[nt] = e; g_tile_row[nt] = start + i * BM; nt++; }
        }
        g_ntiles = nt;
    }

    int t = blockIdx.x * 256 + threadIdx.x;
    if (t < NTOK) {
        int e = g_eid[t];
        int p = atomicAdd(&g_cursor[e], 1);
        g_perm[soff[e] + p] = t;
    }
}

// ---------------- grouped fp16 GEMM (m16n8k16 + ldmatrix, 128x128x64, 3-stage) ----------
// mbarrier producer/consumer pipeline replaces the per-iteration cp_wait+__syncthreads:
// full[s] (count=256) flips via per-thread cp.async.mbarrier.arrive; empty[s] (count=8)
// flips via one arrive per warp after its last LDSM of that stage. Warps drift instead
// of lockstepping. Staging chunks remain interleaved with the MMA steps (round-13 win).
// G1 (FUSEW=true): blocks >= NG1 instead run the W2 convert (overlaps GEMM1's tail).
template<int KTOT, int NTOT, int NT, bool G1, bool FUSEW>
__global__ void __launch_bounds__(256, 2)
moe_gemm_kernel(const __half* __restrict__ WT, const float* __restrict__ bias,
                float* __restrict__ Outglob,
                const float* __restrict__ Wsrc, __half* __restrict__ Wdst) {
    extern __shared__ uint32_t sm32[];

    if (FUSEW) {
        if (blockIdx.x >= NG1) {
            wcvt_body<FDIM, DDIM>(Wsrc, Wdst, blockIdx.x - NG1, (void*)sm32);
            return;
        }
    }

    int mt = blockIdx.x / NT;
    int ntile = blockIdx.x % NT;
    if (mt >= g_ntiles) return;
    int e = g_tile_e[mt];
    int row0 = g_tile_row[mt];
    int rows = g_offsets[e + 1] - row0;
    if (rows > BM) rows = BM;
    int n0 = ntile * BN;

    const __half* Abase = G1 ? g_X16 : g_H16;
    const __half* Bw = WT + (size_t)e * KTOT * NTOT;

    float* sbias = (float*)(sm32 + NSTAGE * STAGE_U32);
    uint32_t shb = (uint32_t)__cvta_generic_to_shared(sm32);
    uint32_t mb = shb + MB_U32 * 4;        // full[s]=mb+s*16, empty[s]=mb+s*16+8

    int tid = threadIdx.x;
    int srow = tid >> 3, j = tid & 7;      // staging: 32 rows/chunk, 16B chunk j

    // A loader: 4 rows/thread (srow + i*32), chunk j (8 halves at k = j*8)
    const __half* aptr[4];
    bool avalid[4];
#pragma unroll
    for (int i = 0; i < 4; i++) {
        int r = srow + i * 32;
        bool v = r < rows;
        int src;
        if (G1) { src = g_perm[row0 + (v ? r : 0)]; avalid[i] = v; }
        else    { src = row0 + r; avalid[i] = true; }   // g_H16 padded
        aptr[i] = Abase + (size_t)src * KTOT + j * 8;
    }
    // B loader: 4 rows/thread (srow + i*32); WT rows are k-contiguous
    const __half* bptr = Bw + (size_t)(n0 + srow) * KTOT + j * 8;

    if (tid < BN) sbias[tid] = bias[(size_t)e * NTOT + n0 + tid];
    if (tid == 0) {
#pragma unroll
        for (int s = 0; s < NSTAGE; s++) {
            mbar_init(mb + s * 16, 256);     // full: all threads cp-arrive
            mbar_init(mb + s * 16 + 8, 8);   // empty: one arrive per warp
        }
    }
    __syncthreads();   // publishes sbias + mbarrier init (only block-wide barrier)

    float c[4][4][4];
#pragma unroll
    for (int mf = 0; mf < 4; mf++)
#pragma unroll
        for (int nf = 0; nf < 4; nf++)
#pragma unroll
            for (int i = 0; i < 4; i++) c[mf][nf][i] = 0.f;

    int wid = tid >> 5, lane = tid & 31;
    int wm = wid & 1, wn = wid >> 1;        // 2 x 4 warp grid, 64x32 warp tile
    int mbase = wm * 64, nbase = wn * 32;
    int g = lane >> 2, t4 = lane & 3;

    // ldmatrix lane address bases (byte addresses into shared space)
    int l7 = lane & 7;
    uint32_t aAddr = shb + (((mbase + l7 + ((lane >> 3) & 1) * 8) * ROWU) + ((lane >> 4) & 1) * 4) * 4;
    uint32_t bAddr = shb + A_TILE_U32 * 4 +
                     (((nbase + l7 + ((lane >> 4) & 1) * 8) * ROWU) + ((lane >> 3) & 1) * 4) * 4;

    constexpr int KT = KTOT / BK;
    constexpr uint32_t STB = STAGE_U32 * 4;   // stage stride in bytes

    // ---- staging: one chunk = 1 A row-set + 1 B row-set (1/4 of a tile) ----
    auto stage_chunk = [&](uint32_t* dst, int k0, int i) {
        cp16(dst + (srow + i * 32) * ROWU + j * 4, aptr[i] + k0, avalid[i]);
        cp16(dst + A_TILE_U32 + (srow + i * 32) * ROWU + j * 4,
             bptr + (size_t)i * 32 * KTOT + k0, true);
    };

    // prologue: stage tiles 0 and 1
#pragma unroll
    for (int i = 0; i < 4; i++) stage_chunk(sm32, 0, i);
    cp_arrive(mb + 0 * 16);
#pragma unroll
    for (int i = 0; i < 4; i++) stage_chunk(sm32 + STAGE_U32, BK, i);
    cp_arrive(mb + 1 * 16);

    int cs = 0, cq = 0;   // consumer stage / quotient (tile t)
    int es = 2, uq = 0;   // producer stage / quotient (tile u = t+2)

    for (int t = 0; t < KT; t++) {
        bool pf = (t + 2 < KT);
        uint32_t* dstp = sm32 + es * STAGE_U32;
        int pk0 = (t + 2) * BK;
        uint32_t sb = cs * STB;

        mbar_wait(mb + cs * 16, cq & 1);   // tile t staged (cp-completion tracked)

#pragma unroll
        for (int ks = 0; ks < 4; ks++) {       // 4 x k16 per 64-K tile
            uint32_t ko = ks * 32;             // 16 halves = 32 bytes
            uint32_t afr[4][4], bfr[2][4];
#pragma unroll
            for (int mf = 0; mf < 4; mf++)
                ldsm4(afr[mf], aAddr + sb + mf * (16 * ROWU * 4) + ko);
#pragma unroll
            for (int np = 0; np < 2; np++)
                ldsm4(bfr[np], bAddr + sb + np * (16 * ROWU * 4) + ko);

            if (ks > 0 && pf) stage_chunk(dstp, pk0, ks - 1);  // drain during MMAs

#pragma unroll
            for (int np = 0; np < 2; np++) {
#pragma unroll
                for (int mf = 0; mf < 4; mf++) {
                    mma16(c[mf][2 * np],     afr[mf], bfr[np][0], bfr[np][1]);
                    mma16(c[mf][2 * np + 1], afr[mf], bfr[np][2], bfr[np][3]);
                }
            }

            // after first k16: ensure stage es is free (readers of tile t-1 done)
            if (ks == 0 && pf && uq >= 1) mbar_wait(mb + es * 16 + 8, (uq - 1) & 1);
        }

        if (lane == 0) mbar_arrive(mb + cs * 16 + 8);   // done reading stage cs

        if (pf) {
            stage_chunk(dstp, pk0, 3);
            cp_arrive(mb + es * 16);                     // full[es] when cps land
            if (++es == NSTAGE) { es = 0; uq++; }
        }
        if (++cs == NSTAGE) { cs = 0; cq++; }
    }

    // ---- epilogue ----
#pragma unroll
    for (int mf = 0; mf < 4; mf++) {
#pragma unroll
        for (int half = 0; half < 2; half++) {
            int ml = mbase + mf * 16 + g + half * 8;
            if (ml >= rows) continue;
            size_t grow;
            float gate = 1.f;
            if (G1) {
                grow = (size_t)(row0 + ml);
            } else {
                int tok = g_perm[row0 + ml];
                gate = g_gate[tok];
                grow = (size_t)tok;
            }
#pragma unroll
            for (int nf = 0; nf < 4; nf++) {
                int nl = nbase + nf * 8 + t4 * 2;
                float vx = c[mf][nf][half * 2 + 0] + sbias[nl];
                float vy = c[mf][nf][half * 2 + 1] + sbias[nl + 1];
                if (G1) {
                    vx = 0.5f * vx * (1.0f + erff(vx * 0.70710678118654752f));
                    vy = 0.5f * vy * (1.0f + erff(vy * 0.70710678118654752f));
                    __half2* orow = (__half2*)(g_H16 + grow * NTOT + n0 + nl);
                    *orow = __floats2half2_rn(vx, vy);
                } else {
                    float2 v = { vx * gate, vy * gate };
                    *(float2*)(Outglob + grow * NTOT + n0 + nl) = v;
                }
            }
        }
    }
}

// ---------------- launch ----------------
// 4 kernels: pre(0: wcvt1+router), scatter(1), GEMM1+wcvt2(2), GEMM2(3 <- ncu profiles this)
extern "C" void kernel_launch(void* const* d_in, const int* in_sizes, int n_in,
                              void* d_out, int out_size) {
    const float* x  = (const float*)d_in[0];
    const float* W1 = (const float*)d_in[1];
    const float* b1 = (const float*)d_in[2];
    const float* W2 = (const float*)d_in[3];
    const float* b2 = (const float*)d_in[4];
    const float* Wr = (const float*)d_in[5];
    const float* br = (const float*)d_in[6];
    float* out = (float*)d_out;

    __half *w1t, *w2t;
    int *cnts, *curs;
    cudaGetSymbolAddress((void**)&w1t, g_W1T);
    cudaGetSymbolAddress((void**)&w2t, g_W2T);
    cudaGetSymbolAddress((void**)&cnts, g_counts);
    cudaGetSymbolAddress((void**)&curs, g_cursor);

    cudaFuncSetAttribute(moe_gemm_kernel<DDIM, FDIM, FDIM/BN, true, true>,
                         cudaFuncAttributeMaxDynamicSharedMemorySize, SMEM_BYTES);
    cudaFuncSetAttribute(moe_gemm_kernel<FDIM, DDIM, DDIM/BN, false, false>,
                         cudaFuncAttributeMaxDynamicSharedMemorySize, SMEM_BYTES);

    cudaMemsetAsync(cnts, 0, NEXP * sizeof(int));
    cudaMemsetAsync(curs, 0, NEXP * sizeof(int));

    pre_kernel<<<WC1_BLOCKS + NTOK / 8, 256>>>(x, Wr, br, W1, w1t);
    scatter_kernel<<<NTOK / 256, 256>>>();

    moe_gemm_kernel<DDIM, FDIM, FDIM/BN, true, true>
        <<<NG1 + WC2_BLOCKS, 256, SMEM_BYTES>>>(w1t, b1, nullptr, W2, w2t);

    moe_gemm_kernel<FDIM, DDIM, DDIM/BN, false, false>
        <<<(DDIM/BN) * MAXTILES, 256, SMEM_BYTES>>>(w2t, b2, out, nullptr, nullptr);
}